// round 7
// baseline (speedup 1.0000x reference)
#include <cuda_runtime.h>
#include <cstdint>
#include <cstddef>

// ---------------------------------------------------------------------------
// QDense == one dense 4096x4096x4096 GEMM:
//     out[m,n] = sum_k x[m,k] * Weff[n,k] + bias_eff[n]
// Weff[co*1024+o][ci*1024+i] = S[co][ci] * W_{Q[co][ci]}[o][i]
//
// tf32 mma.sync.m16n8k8 + fp32 accum, cp.async 3-stage pipeline.
// R6: 512 threads / 16 warps (warp tile 32x64) to lift occupancy 12.5%->25%;
//     profile showed latency-bound (tensor 50%, L2 22%, occ 12.5%).
// ---------------------------------------------------------------------------

#define IN_F   4096
#define OUT_F  4096
#define BATCH  4096
#define QOUT   1024                   // OUT_Q: per-component bias length
#define W_ELEMS (1024 * 1024)

#define BM 128
#define BN 256
#define BK 32                         // k-floats per stage
#define STAGES 3
#define KTILES (IN_F / BK)            // 128
#define THREADS 512

#define PADS 36                       // padded row stride in floats
#define ROWB (PADS * 4)               // 144 bytes per row
#define A_ST_BYTES (BM * ROWB)        // 18432
#define B_ST_BYTES (BN * ROWB)        // 36864
#define STAGE_BYTES (A_ST_BYTES + B_ST_BYTES)    // 55296
#define SMEM_TOTAL (STAGES * STAGE_BYTES)        // 165888

// Scratch: device globals (the only legal scratch)
__device__ float g_xr  [(size_t)BATCH * IN_F];   // tf32-rounded x     (64 MB)
__device__ float g_weff[(size_t)OUT_F * IN_F];   // tf32-rounded Weff  (64 MB)
__device__ float g_bias[OUT_F];

__constant__ int   c_q[4][4] = {{0,1,2,3},{1,0,3,2},{2,3,0,1},{3,2,1,0}};
__constant__ float c_s[4][4] = {{ 1.f,-1.f,-1.f,-1.f},
                                { 1.f, 1.f, 1.f,-1.f},
                                { 1.f,-1.f, 1.f, 1.f},
                                { 1.f, 1.f,-1.f, 1.f}};

// ------------------------------- helpers -----------------------------------

__device__ __forceinline__ uint32_t smem_u32(const void* p) {
    uint32_t a;
    asm("{ .reg .u64 t; cvta.to.shared.u64 t, %1; cvt.u32.u64 %0, t; }"
        : "=r"(a) : "l"(p));
    return a;
}

__device__ __forceinline__ void cp16(uint32_t dst, const float* src) {
    asm volatile("cp.async.cg.shared.global [%0], [%1], 16;" :: "r"(dst), "l"(src));
}

__device__ __forceinline__ void cp_commit() {
    asm volatile("cp.async.commit_group;" ::: "memory");
}

template <int N>
__device__ __forceinline__ void cp_wait() {
    asm volatile("cp.async.wait_group %0;" :: "n"(N) : "memory");
}

__device__ __forceinline__ uint32_t lds32(uint32_t addr) {
    uint32_t v;
    asm volatile("ld.shared.b32 %0, [%1];" : "=r"(v) : "r"(addr));
    return v;
}

__device__ __forceinline__ void mma_tf32(float* d, const uint32_t* a,
                                         uint32_t b0, uint32_t b1) {
    asm volatile(
        "mma.sync.aligned.m16n8k8.row.col.f32.tf32.tf32.f32 "
        "{%0,%1,%2,%3}, {%4,%5,%6,%7}, {%8,%9}, {%0,%1,%2,%3};"
        : "+f"(d[0]), "+f"(d[1]), "+f"(d[2]), "+f"(d[3])
        : "r"(a[0]), "r"(a[1]), "r"(a[2]), "r"(a[3]), "r"(b0), "r"(b1));
}

__device__ __forceinline__ float rna_tf32(float x) {
    uint32_t u;
    asm("cvt.rna.tf32.f32 %0, %1;" : "=r"(u) : "f"(x));
    return __uint_as_float(u);
}

// ------------------------------ prep kernels --------------------------------

__global__ void k_round_x(const float* __restrict__ x) {
    size_t i = (size_t)blockIdx.x * blockDim.x + threadIdx.x;   // float4 idx
    float4 v = ((const float4*)x)[i];
    v.x = rna_tf32(v.x); v.y = rna_tf32(v.y);
    v.z = rna_tf32(v.z); v.w = rna_tf32(v.w);
    ((float4*)g_xr)[i] = v;
}

__global__ void k_weff(const float* __restrict__ W0, const float* __restrict__ W1,
                       const float* __restrict__ W2, const float* __restrict__ W3) {
    size_t id = (size_t)blockIdx.x * blockDim.x + threadIdx.x;  // float4 idx
    int n  = (int)(id >> 10);        // output row (0..4095); 1024 float4/row
    int k4 = (int)(id & 1023);
    int co = n >> 10, o = n & 1023;
    int ci = k4 >> 8;
    int i4 = k4 & 255;
    int q   = c_q[co][ci];
    float s = c_s[co][ci];
    const float* Wq = (q == 0) ? W0 : (q == 1) ? W1 : (q == 2) ? W2 : W3;
    float4 w = ((const float4*)Wq)[(size_t)o * 256 + i4];
    float4 r;
    r.x = s * rna_tf32(w.x); r.y = s * rna_tf32(w.y);
    r.z = s * rna_tf32(w.z); r.w = s * rna_tf32(w.w);
    ((float4*)g_weff)[id] = r;
}

__global__ void k_bias(const float* __restrict__ b0, const float* __restrict__ b1,
                       const float* __restrict__ b2, const float* __restrict__ b3) {
    int n = blockIdx.x * blockDim.x + threadIdx.x;
    if (n >= OUT_F) return;
    int co = n >> 10, o = n & 1023;
    const float* B[4] = {b0, b1, b2, b3};
    float acc = 0.f;
#pragma unroll
    for (int ci = 0; ci < 4; ci++) acc += c_s[co][ci] * B[c_q[co][ci]][o];
    g_bias[n] = acc;
}

// ------------------------------- GEMM kernel --------------------------------

__device__ __forceinline__ void load_stage(uint32_t sb, int slot, int kt,
                                           const float* __restrict__ aG,
                                           const float* __restrict__ bG,
                                           int tid) {
    const uint32_t st = sb + slot * STAGE_BYTES;
    const int koff = kt * BK;
    // A: 128 rows x 8 chunks of 16B = 1024 chunks; 2 per thread
#pragma unroll
    for (int j = 0; j < 2; j++) {
        int c   = tid + j * THREADS;
        int row = c >> 3;
        int ko  = c & 7;
        cp16(st + row * ROWB + ko * 16, aG + (size_t)row * IN_F + koff + ko * 4);
    }
    // B: 256 rows x 8 chunks = 2048 chunks; 4 per thread
#pragma unroll
    for (int j = 0; j < 4; j++) {
        int c   = tid + j * THREADS;
        int row = c >> 3;
        int ko  = c & 7;
        cp16(st + A_ST_BYTES + row * ROWB + ko * 16,
             bG + (size_t)row * IN_F + koff + ko * 4);
    }
}

__global__ void __launch_bounds__(THREADS, 1) k_gemm(float* __restrict__ out) {
    extern __shared__ char smem[];
    const uint32_t sb = smem_u32(smem);
    const int tid = threadIdx.x;
    const int wid = tid >> 5;
    const int lid = tid & 31;
    const int m0 = blockIdx.y * BM;
    const int n0 = blockIdx.x * BN;

    const int wm = wid & 3;            // 4 m-warps (32 rows each)
    const int wn = wid >> 2;           // 4 n-warps (64 cols each)
    const int gid = lid >> 2;          // 0..7
    const int tig = lid & 3;           // 0..3

    const float* aG = g_xr   + (size_t)m0 * IN_F;
    const float* bG = g_weff + (size_t)n0 * IN_F;

    // fragment base addresses within a stage (stage offset added per iter)
    const uint32_t aBase = sb + (uint32_t)(wm * 32 + gid) * ROWB + tig * 4;
    const uint32_t bBase = sb + A_ST_BYTES
                         + (uint32_t)(wn * 64 + gid) * ROWB + tig * 4;

    float acc[2][8][4];
#pragma unroll
    for (int mf = 0; mf < 2; mf++)
#pragma unroll
        for (int nf = 0; nf < 8; nf++)
#pragma unroll
            for (int r = 0; r < 4; r++) acc[mf][nf][r] = 0.f;

    // prologue: stages 0,1
    load_stage(sb, 0, 0, aG, bG, tid); cp_commit();
    load_stage(sb, 1, 1, aG, bG, tid); cp_commit();

    int slot = 0;
    for (int kt = 0; kt < KTILES; kt++) {
        cp_wait<1>();
        __syncthreads();   // data ready + everyone done with the slot being refilled

        // issue next-next stage into the slot freed last iteration
        if (kt + 2 < KTILES) {
            int ns = slot + 2; if (ns >= STAGES) ns -= STAGES;
            load_stage(sb, ns, kt + 2, aG, bG, tid);
        }
        cp_commit();

        const uint32_t aS = aBase + slot * STAGE_BYTES;
        const uint32_t bS = bBase + slot * STAGE_BYTES;

#pragma unroll
        for (int kk = 0; kk < 4; kk++) {
            uint32_t a[2][4];
#pragma unroll
            for (int mf = 0; mf < 2; mf++) {
                uint32_t base = aS + mf * (16 * ROWB) + kk * 32;
                a[mf][0] = lds32(base);
                a[mf][1] = lds32(base + 8 * ROWB);
                a[mf][2] = lds32(base + 16);
                a[mf][3] = lds32(base + 8 * ROWB + 16);
            }
#pragma unroll
            for (int nf = 0; nf < 8; nf++) {
                uint32_t bb = bS + nf * (8 * ROWB) + kk * 32;
                uint32_t b0 = lds32(bb);
                uint32_t b1 = lds32(bb + 16);
#pragma unroll
                for (int mf = 0; mf < 2; mf++)
                    mma_tf32(acc[mf][nf], a[mf], b0, b1);
            }
        }

        slot++; if (slot >= STAGES) slot = 0;
        // no trailing sync: next iteration's top barrier protects slot reuse
    }

    // ---- epilogue: acc + bias -> out ----
    // fragment (mf,nf): rows m0+wm*32+mf*16+gid (+8), cols n0+wn*64+nf*8+tig*2
    float2 bv[8];
#pragma unroll
    for (int nf = 0; nf < 8; nf++) {
        const float* bp = g_bias + n0 + wn * 64 + nf * 8 + tig * 2;
        bv[nf] = make_float2(bp[0], bp[1]);
    }
#pragma unroll
    for (int mf = 0; mf < 2; mf++) {
        int r0 = m0 + wm * 32 + mf * 16 + gid;
#pragma unroll
        for (int nf = 0; nf < 8; nf++) {
            int c = n0 + wn * 64 + nf * 8 + tig * 2;
            float2 v0 = make_float2(acc[mf][nf][0] + bv[nf].x,
                                    acc[mf][nf][1] + bv[nf].y);
            float2 v1 = make_float2(acc[mf][nf][2] + bv[nf].x,
                                    acc[mf][nf][3] + bv[nf].y);
            *(float2*)(out + (size_t)r0 * OUT_F + c)       = v0;
            *(float2*)(out + (size_t)(r0 + 8) * OUT_F + c) = v1;
        }
    }
}

// ------------------------------- launcher -----------------------------------

extern "C" void kernel_launch(void* const* d_in, const int* in_sizes, int n_in,
                              void* d_out, int out_size) {
    // Identify inputs by element count (robust to metadata ordering):
    //   x: 16777216;  W_*: 1048576 each;  b_*: 1024 each (OUT_Q)
    const float* x = nullptr;
    const float* W[4] = {nullptr, nullptr, nullptr, nullptr};
    const float* b[4] = {nullptr, nullptr, nullptr, nullptr};
    int wn = 0, bn = 0;
    for (int i = 0; i < n_in; i++) {
        if (in_sizes[i] == BATCH * IN_F)    x = (const float*)d_in[i];
        else if (in_sizes[i] == W_ELEMS)    { if (wn < 4) W[wn++] = (const float*)d_in[i]; }
        else if (in_sizes[i] == QOUT)       { if (bn < 4) b[bn++] = (const float*)d_in[i]; }
    }
    if (!x || wn != 4 || bn != 4) return;

    cudaFuncSetAttribute(k_gemm, cudaFuncAttributeMaxDynamicSharedMemorySize,
                         SMEM_TOTAL);

    k_round_x<<<(BATCH * IN_F / 4) / 256, 256>>>(x);
    k_weff<<<(int)(((size_t)OUT_F * IN_F / 4) / 256), 256>>>(W[0], W[1], W[2], W[3]);
    k_bias<<<OUT_F / 256, 256>>>(b[0], b[1], b[2], b[3]);

    dim3 grid(OUT_F / BN, BATCH / BM);
    k_gemm<<<grid, THREADS, SMEM_TOTAL>>>((float*)d_out);
}

// round 8
// speedup vs baseline: 1.8984x; 1.8984x over previous
#include <cuda_runtime.h>
#include <cuda_fp16.h>
#include <cstdint>
#include <cstddef>

// ---------------------------------------------------------------------------
// QDense == one dense 4096x4096x4096 GEMM:
//     out[m,n] = sum_k x[m,k] * Weff[n,k] + bias_eff[n]
// Weff[co*1024+o][ci*1024+i] = S[co][ci] * W_{Q[co][ci]}[o][i]
//
// R7: tf32 HMMA proved rate-capped at 50% of pipe peak (2 configs, identical
//     tensor% and dur). Switch to fp16 m16n8k16 (same 10-bit mantissa as tf32,
//     2x MACs/instruction) with fp32 accumulation. cp.async 3-stage pipeline.
// ---------------------------------------------------------------------------

#define IN_F   4096
#define OUT_F  4096
#define BATCH  4096
#define QOUT   1024                   // OUT_Q: per-component bias length
#define W_ELEMS (1024 * 1024)

#define BM 128
#define BN 256
#define BK 64                         // k half-elements per stage (128 B rows)
#define STAGES 3
#define KTILES (IN_F / BK)            // 64
#define THREADS 512

#define ROWB 144                      // padded row stride in bytes (72 halves)
#define A_ST_BYTES (BM * ROWB)        // 18432
#define B_ST_BYTES (BN * ROWB)        // 36864
#define STAGE_BYTES (A_ST_BYTES + B_ST_BYTES)    // 55296
#define SMEM_TOTAL (STAGES * STAGE_BYTES)        // 165888

// Scratch: device globals (the only legal scratch)
__device__ __half g_xh[(size_t)BATCH * IN_F];    // fp16 x     (32 MB)
__device__ __half g_wh[(size_t)OUT_F * IN_F];    // fp16 Weff  (32 MB)
__device__ float  g_bias[OUT_F];

__constant__ int   c_q[4][4] = {{0,1,2,3},{1,0,3,2},{2,3,0,1},{3,2,1,0}};
__constant__ float c_s[4][4] = {{ 1.f,-1.f,-1.f,-1.f},
                                { 1.f, 1.f, 1.f,-1.f},
                                { 1.f,-1.f, 1.f, 1.f},
                                { 1.f, 1.f,-1.f, 1.f}};

// ------------------------------- helpers -----------------------------------

__device__ __forceinline__ uint32_t smem_u32(const void* p) {
    uint32_t a;
    asm("{ .reg .u64 t; cvta.to.shared.u64 t, %1; cvt.u32.u64 %0, t; }"
        : "=r"(a) : "l"(p));
    return a;
}

__device__ __forceinline__ void cp16(uint32_t dst, const void* src) {
    asm volatile("cp.async.cg.shared.global [%0], [%1], 16;" :: "r"(dst), "l"(src));
}

__device__ __forceinline__ void cp_commit() {
    asm volatile("cp.async.commit_group;" ::: "memory");
}

template <int N>
__device__ __forceinline__ void cp_wait() {
    asm volatile("cp.async.wait_group %0;" :: "n"(N) : "memory");
}

__device__ __forceinline__ uint32_t lds32(uint32_t addr) {
    uint32_t v;
    asm volatile("ld.shared.b32 %0, [%1];" : "=r"(v) : "r"(addr));
    return v;
}

// fp16 m16n8k16, row.col, fp32 accumulate
__device__ __forceinline__ void mma_f16(float* d, const uint32_t* a,
                                        uint32_t b0, uint32_t b1) {
    asm volatile(
        "mma.sync.aligned.m16n8k16.row.col.f32.f16.f16.f32 "
        "{%0,%1,%2,%3}, {%4,%5,%6,%7}, {%8,%9}, {%0,%1,%2,%3};"
        : "+f"(d[0]), "+f"(d[1]), "+f"(d[2]), "+f"(d[3])
        : "r"(a[0]), "r"(a[1]), "r"(a[2]), "r"(a[3]), "r"(b0), "r"(b1));
}

// ------------------------------ prep kernels --------------------------------

__global__ void k_half_x(const float* __restrict__ x) {
    size_t i = (size_t)blockIdx.x * blockDim.x + threadIdx.x;   // float4 idx
    float4 v = ((const float4*)x)[i];
    __half2 h0 = make_half2(__float2half_rn(v.x), __float2half_rn(v.y));
    __half2 h1 = make_half2(__float2half_rn(v.z), __float2half_rn(v.w));
    ((__half2*)g_xh)[2 * i]     = h0;
    ((__half2*)g_xh)[2 * i + 1] = h1;
}

__global__ void k_weff(const float* __restrict__ W0, const float* __restrict__ W1,
                       const float* __restrict__ W2, const float* __restrict__ W3) {
    size_t id = (size_t)blockIdx.x * blockDim.x + threadIdx.x;  // float4 idx
    int n  = (int)(id >> 10);        // output row (0..4095); 1024 float4/row
    int k4 = (int)(id & 1023);
    int co = n >> 10, o = n & 1023;
    int ci = k4 >> 8;
    int i4 = k4 & 255;
    int q   = c_q[co][ci];
    float s = c_s[co][ci];
    const float* Wq = (q == 0) ? W0 : (q == 1) ? W1 : (q == 2) ? W2 : W3;
    float4 w = ((const float4*)Wq)[(size_t)o * 256 + i4];
    __half2 h0 = make_half2(__float2half_rn(s * w.x), __float2half_rn(s * w.y));
    __half2 h1 = make_half2(__float2half_rn(s * w.z), __float2half_rn(s * w.w));
    ((__half2*)g_wh)[2 * id]     = h0;
    ((__half2*)g_wh)[2 * id + 1] = h1;
}

__global__ void k_bias(const float* __restrict__ b0, const float* __restrict__ b1,
                       const float* __restrict__ b2, const float* __restrict__ b3) {
    int n = blockIdx.x * blockDim.x + threadIdx.x;
    if (n >= OUT_F) return;
    int co = n >> 10, o = n & 1023;
    const float* B[4] = {b0, b1, b2, b3};
    float acc = 0.f;
#pragma unroll
    for (int ci = 0; ci < 4; ci++) acc += c_s[co][ci] * B[c_q[co][ci]][o];
    g_bias[n] = acc;
}

// ------------------------------- GEMM kernel --------------------------------

__device__ __forceinline__ void load_stage(uint32_t sb, int slot, int kt,
                                           const __half* __restrict__ aG,
                                           const __half* __restrict__ bG,
                                           int tid) {
    const uint32_t st = sb + slot * STAGE_BYTES;
    const int koff = kt * BK;        // in half-elements
    // A: 128 rows x 8 chunks of 16B (= 8 halves each); 1024 chunks; 2/thread
#pragma unroll
    for (int j = 0; j < 2; j++) {
        int c   = tid + j * THREADS;
        int row = c >> 3;
        int ko  = c & 7;
        cp16(st + row * ROWB + ko * 16,
             aG + (size_t)row * IN_F + koff + ko * 8);
    }
    // B: 256 rows x 8 chunks = 2048 chunks; 4/thread
#pragma unroll
    for (int j = 0; j < 4; j++) {
        int c   = tid + j * THREADS;
        int row = c >> 3;
        int ko  = c & 7;
        cp16(st + A_ST_BYTES + row * ROWB + ko * 16,
             bG + (size_t)row * IN_F + koff + ko * 8);
    }
}

__global__ void __launch_bounds__(THREADS, 1) k_gemm(float* __restrict__ out) {
    extern __shared__ char smem[];
    const uint32_t sb = smem_u32(smem);
    const int tid = threadIdx.x;
    const int wid = tid >> 5;
    const int lid = tid & 31;
    const int m0 = blockIdx.y * BM;
    const int n0 = blockIdx.x * BN;

    const int wm = wid & 3;            // 4 m-warps (32 rows each)
    const int wn = wid >> 2;           // 4 n-warps (64 cols each)
    const int gid = lid >> 2;          // 0..7
    const int tig = lid & 3;           // 0..3

    const __half* aG = g_xh + (size_t)m0 * IN_F;
    const __half* bG = g_wh + (size_t)n0 * IN_F;

    // fragment base addresses within a stage; tig*4 bytes = halves {2t,2t+1}
    const uint32_t aBase = sb + (uint32_t)(wm * 32 + gid) * ROWB + tig * 4;
    const uint32_t bBase = sb + A_ST_BYTES
                         + (uint32_t)(wn * 64 + gid) * ROWB + tig * 4;

    float acc[2][8][4];
#pragma unroll
    for (int mf = 0; mf < 2; mf++)
#pragma unroll
        for (int nf = 0; nf < 8; nf++)
#pragma unroll
            for (int r = 0; r < 4; r++) acc[mf][nf][r] = 0.f;

    // prologue: stages 0,1
    load_stage(sb, 0, 0, aG, bG, tid); cp_commit();
    load_stage(sb, 1, 1, aG, bG, tid); cp_commit();

    int slot = 0;
    for (int kt = 0; kt < KTILES; kt++) {
        cp_wait<1>();
        __syncthreads();   // data ready + slot-being-refilled drained

        if (kt + 2 < KTILES) {
            int ns = slot + 2; if (ns >= STAGES) ns -= STAGES;
            load_stage(sb, ns, kt + 2, aG, bG, tid);
        }
        cp_commit();

        const uint32_t aS = aBase + slot * STAGE_BYTES;
        const uint32_t bS = bBase + slot * STAGE_BYTES;

        // 4 x k16 chunks per stage; kk byte offset = kk*32 (16 halves)
#pragma unroll
        for (int kk = 0; kk < 4; kk++) {
            uint32_t a[2][4];
#pragma unroll
            for (int mf = 0; mf < 2; mf++) {
                uint32_t base = aS + mf * (16 * ROWB) + kk * 32;
                a[mf][0] = lds32(base);                 // row g,   k {2t,2t+1}
                a[mf][1] = lds32(base + 8 * ROWB);      // row g+8
                a[mf][2] = lds32(base + 16);            // row g,   k +8
                a[mf][3] = lds32(base + 8 * ROWB + 16); // row g+8, k +8
            }
#pragma unroll
            for (int nf = 0; nf < 8; nf++) {
                uint32_t bb = bS + nf * (8 * ROWB) + kk * 32;
                uint32_t b0 = lds32(bb);                // col g, k {2t,2t+1}
                uint32_t b1 = lds32(bb + 16);           // col g, k +8
#pragma unroll
                for (int mf = 0; mf < 2; mf++)
                    mma_f16(acc[mf][nf], a[mf], b0, b1);
            }
        }

        slot++; if (slot >= STAGES) slot = 0;
    }

    // ---- epilogue: acc + bias -> out ----
    float2 bv[8];
#pragma unroll
    for (int nf = 0; nf < 8; nf++) {
        const float* bp = g_bias + n0 + wn * 64 + nf * 8 + tig * 2;
        bv[nf] = make_float2(bp[0], bp[1]);
    }
#pragma unroll
    for (int mf = 0; mf < 2; mf++) {
        int r0 = m0 + wm * 32 + mf * 16 + gid;
#pragma unroll
        for (int nf = 0; nf < 8; nf++) {
            int c = n0 + wn * 64 + nf * 8 + tig * 2;
            float2 v0 = make_float2(acc[mf][nf][0] + bv[nf].x,
                                    acc[mf][nf][1] + bv[nf].y);
            float2 v1 = make_float2(acc[mf][nf][2] + bv[nf].x,
                                    acc[mf][nf][3] + bv[nf].y);
            *(float2*)(out + (size_t)r0 * OUT_F + c)       = v0;
            *(float2*)(out + (size_t)(r0 + 8) * OUT_F + c) = v1;
        }
    }
}

// ------------------------------- launcher -----------------------------------

extern "C" void kernel_launch(void* const* d_in, const int* in_sizes, int n_in,
                              void* d_out, int out_size) {
    // Identify inputs by element count (robust to metadata ordering):
    //   x: 16777216;  W_*: 1048576 each;  b_*: 1024 each (OUT_Q)
    const float* x = nullptr;
    const float* W[4] = {nullptr, nullptr, nullptr, nullptr};
    const float* b[4] = {nullptr, nullptr, nullptr, nullptr};
    int wn = 0, bn = 0;
    for (int i = 0; i < n_in; i++) {
        if (in_sizes[i] == BATCH * IN_F)    x = (const float*)d_in[i];
        else if (in_sizes[i] == W_ELEMS)    { if (wn < 4) W[wn++] = (const float*)d_in[i]; }
        else if (in_sizes[i] == QOUT)       { if (bn < 4) b[bn++] = (const float*)d_in[i]; }
    }
    if (!x || wn != 4 || bn != 4) return;

    cudaFuncSetAttribute(k_gemm, cudaFuncAttributeMaxDynamicSharedMemorySize,
                         SMEM_TOTAL);

    k_half_x<<<(BATCH * IN_F / 4) / 256, 256>>>(x);
    k_weff<<<(int)(((size_t)OUT_F * IN_F / 4) / 256), 256>>>(W[0], W[1], W[2], W[3]);
    k_bias<<<OUT_F / 256, 256>>>(b[0], b[1], b[2], b[3]);

    dim3 grid(OUT_F / BN, BATCH / BM);
    k_gemm<<<grid, THREADS, SMEM_TOTAL>>>((float*)d_out);
}

// round 9
// speedup vs baseline: 2.0662x; 1.0883x over previous
#include <cuda_runtime.h>
#include <cuda_fp16.h>
#include <cstdint>
#include <cstddef>

// ---------------------------------------------------------------------------
// QDense == one dense 4096x4096x4096 GEMM:
//     out[m,n] = sum_k x[m,k] * Weff[n,k] + bias_eff[n]
// Weff[co*1024+o][ci*1024+i] = S[co][ci] * W_{Q[co][ci]}[o][i]
//
// R8->R9: fp16 m16n8k16 confirmed 2x over tf32 (493us). HMMA issue rate is
//   pinned at 1/16cyc/SMSP across configs with tensor%=49 -> test whether the
//   limiter is LDS/issue pressure by replacing 24 lds32/kk with 6 ldmatrix.x4.
// ---------------------------------------------------------------------------

#define IN_F   4096
#define OUT_F  4096
#define BATCH  4096
#define QOUT   1024
#define W_ELEMS (1024 * 1024)

#define BM 128
#define BN 256
#define BK 64                         // k half-elements per stage (128 B rows)
#define STAGES 3
#define KTILES (IN_F / BK)            // 64
#define THREADS 512

#define ROWB 144                      // padded row stride in bytes (72 halves)
#define A_ST_BYTES (BM * ROWB)        // 18432
#define B_ST_BYTES (BN * ROWB)        // 36864
#define STAGE_BYTES (A_ST_BYTES + B_ST_BYTES)    // 55296
#define SMEM_TOTAL (STAGES * STAGE_BYTES)        // 165888

// Scratch: device globals (the only legal scratch)
__device__ __half g_xh[(size_t)BATCH * IN_F];    // fp16 x     (32 MB)
__device__ __half g_wh[(size_t)OUT_F * IN_F];    // fp16 Weff  (32 MB)
__device__ float  g_bias[OUT_F];

__constant__ int   c_q[4][4] = {{0,1,2,3},{1,0,3,2},{2,3,0,1},{3,2,1,0}};
__constant__ float c_s[4][4] = {{ 1.f,-1.f,-1.f,-1.f},
                                { 1.f, 1.f, 1.f,-1.f},
                                { 1.f,-1.f, 1.f, 1.f},
                                { 1.f, 1.f,-1.f, 1.f}};

// ------------------------------- helpers -----------------------------------

__device__ __forceinline__ uint32_t smem_u32(const void* p) {
    uint32_t a;
    asm("{ .reg .u64 t; cvta.to.shared.u64 t, %1; cvt.u32.u64 %0, t; }"
        : "=r"(a) : "l"(p));
    return a;
}

__device__ __forceinline__ void cp16(uint32_t dst, const void* src) {
    asm volatile("cp.async.cg.shared.global [%0], [%1], 16;" :: "r"(dst), "l"(src));
}

__device__ __forceinline__ void cp_commit() {
    asm volatile("cp.async.commit_group;" ::: "memory");
}

template <int N>
__device__ __forceinline__ void cp_wait() {
    asm volatile("cp.async.wait_group %0;" :: "n"(N) : "memory");
}

// ldmatrix x4: four 8x8 b16 tiles; per-lane row addresses
__device__ __forceinline__ void ldmx4(uint32_t* r, uint32_t addr) {
    asm volatile(
        "ldmatrix.sync.aligned.m8n8.x4.shared.b16 {%0,%1,%2,%3}, [%4];"
        : "=r"(r[0]), "=r"(r[1]), "=r"(r[2]), "=r"(r[3]) : "r"(addr));
}

// fp16 m16n8k16, row.col, fp32 accumulate
__device__ __forceinline__ void mma_f16(float* d, const uint32_t* a,
                                        uint32_t b0, uint32_t b1) {
    asm volatile(
        "mma.sync.aligned.m16n8k16.row.col.f32.f16.f16.f32 "
        "{%0,%1,%2,%3}, {%4,%5,%6,%7}, {%8,%9}, {%0,%1,%2,%3};"
        : "+f"(d[0]), "+f"(d[1]), "+f"(d[2]), "+f"(d[3])
        : "r"(a[0]), "r"(a[1]), "r"(a[2]), "r"(a[3]), "r"(b0), "r"(b1));
}

// ------------------------------ prep kernels --------------------------------

__global__ void k_half_x(const float* __restrict__ x) {
    size_t i = (size_t)blockIdx.x * blockDim.x + threadIdx.x;   // float4 idx
    float4 v = ((const float4*)x)[i];
    __half2 h0 = make_half2(__float2half_rn(v.x), __float2half_rn(v.y));
    __half2 h1 = make_half2(__float2half_rn(v.z), __float2half_rn(v.w));
    ((__half2*)g_xh)[2 * i]     = h0;
    ((__half2*)g_xh)[2 * i + 1] = h1;
}

__global__ void k_weff(const float* __restrict__ W0, const float* __restrict__ W1,
                       const float* __restrict__ W2, const float* __restrict__ W3) {
    size_t id = (size_t)blockIdx.x * blockDim.x + threadIdx.x;  // float4 idx
    int n  = (int)(id >> 10);
    int k4 = (int)(id & 1023);
    int co = n >> 10, o = n & 1023;
    int ci = k4 >> 8;
    int i4 = k4 & 255;
    int q   = c_q[co][ci];
    float s = c_s[co][ci];
    const float* Wq = (q == 0) ? W0 : (q == 1) ? W1 : (q == 2) ? W2 : W3;
    float4 w = ((const float4*)Wq)[(size_t)o * 256 + i4];
    __half2 h0 = make_half2(__float2half_rn(s * w.x), __float2half_rn(s * w.y));
    __half2 h1 = make_half2(__float2half_rn(s * w.z), __float2half_rn(s * w.w));
    ((__half2*)g_wh)[2 * id]     = h0;
    ((__half2*)g_wh)[2 * id + 1] = h1;
}

__global__ void k_bias(const float* __restrict__ b0, const float* __restrict__ b1,
                       const float* __restrict__ b2, const float* __restrict__ b3) {
    int n = blockIdx.x * blockDim.x + threadIdx.x;
    if (n >= OUT_F) return;
    int co = n >> 10, o = n & 1023;
    const float* B[4] = {b0, b1, b2, b3};
    float acc = 0.f;
#pragma unroll
    for (int ci = 0; ci < 4; ci++) acc += c_s[co][ci] * B[c_q[co][ci]][o];
    g_bias[n] = acc;
}

// ------------------------------- GEMM kernel --------------------------------

__device__ __forceinline__ void load_stage(uint32_t sb, int slot, int kt,
                                           const __half* __restrict__ aG,
                                           const __half* __restrict__ bG,
                                           int tid) {
    const uint32_t st = sb + slot * STAGE_BYTES;
    const int koff = kt * BK;        // in half-elements
#pragma unroll
    for (int j = 0; j < 2; j++) {
        int c   = tid + j * THREADS;
        int row = c >> 3;
        int ko  = c & 7;
        cp16(st + row * ROWB + ko * 16,
             aG + (size_t)row * IN_F + koff + ko * 8);
    }
#pragma unroll
    for (int j = 0; j < 4; j++) {
        int c   = tid + j * THREADS;
        int row = c >> 3;
        int ko  = c & 7;
        cp16(st + A_ST_BYTES + row * ROWB + ko * 16,
             bG + (size_t)row * IN_F + koff + ko * 8);
    }
}

__global__ void __launch_bounds__(THREADS, 1) k_gemm(float* __restrict__ out) {
    extern __shared__ char smem[];
    const uint32_t sb = smem_u32(smem);
    const int tid = threadIdx.x;
    const int wid = tid >> 5;
    const int lid = tid & 31;
    const int m0 = blockIdx.y * BM;
    const int n0 = blockIdx.x * BN;

    const int wm = wid & 3;            // 4 m-warps (32 rows each)
    const int wn = wid >> 2;           // 4 n-warps (64 cols each)
    const int gid = lid >> 2;          // 0..7
    const int tig = lid & 3;           // 0..3

    const __half* aG = g_xh + (size_t)m0 * IN_F;
    const __half* bG = g_wh + (size_t)n0 * IN_F;

    // ---- ldmatrix per-lane base addresses (within stage 0) ----
    // A x4 tile (16x16): lane -> row (lid&15), k-group (lid>>4)*16B
    const uint32_t aL0 = sb
        + (uint32_t)(wm * 32 + (lid & 15)) * ROWB + (uint32_t)(lid >> 4) * 16;
    // A tile mf=1 is +16 rows
    // B x4 (two 8-col n-tiles x k16): lane -> nrow (lid>>4)*8+(lid&7),
    //   k-group ((lid>>3)&1)*16B
    const uint32_t bL0 = sb + A_ST_BYTES
        + (uint32_t)(wn * 64 + ((lid >> 4) * 8) + (lid & 7)) * ROWB
        + (uint32_t)((lid >> 3) & 1) * 16;

    float acc[2][8][4];
#pragma unroll
    for (int mf = 0; mf < 2; mf++)
#pragma unroll
        for (int nf = 0; nf < 8; nf++)
#pragma unroll
            for (int r = 0; r < 4; r++) acc[mf][nf][r] = 0.f;

    // prologue: stages 0,1
    load_stage(sb, 0, 0, aG, bG, tid); cp_commit();
    load_stage(sb, 1, 1, aG, bG, tid); cp_commit();

    int slot = 0;
    for (int kt = 0; kt < KTILES; kt++) {
        cp_wait<1>();
        __syncthreads();   // data ready + slot-being-refilled drained

        if (kt + 2 < KTILES) {
            int ns = slot + 2; if (ns >= STAGES) ns -= STAGES;
            load_stage(sb, ns, kt + 2, aG, bG, tid);
        }
        cp_commit();

        const uint32_t aS = aL0 + slot * STAGE_BYTES;
        const uint32_t bS = bL0 + slot * STAGE_BYTES;

        // 4 x k16 chunks per stage; kk byte offset = kk*32 (16 halves)
#pragma unroll
        for (int kk = 0; kk < 4; kk++) {
            uint32_t a[2][4];
            ldmx4(a[0], aS + kk * 32);                 // rows wm*32..+15
            ldmx4(a[1], aS + 16 * ROWB + kk * 32);     // rows +16..+31
#pragma unroll
            for (int np = 0; np < 4; np++) {           // pairs of n-tiles
                uint32_t bq[4];
                ldmx4(bq, bS + np * (16 * ROWB) + kk * 32);
                // bq = {b0(nf=2np), b1(2np), b0(2np+1), b1(2np+1)}
                mma_f16(acc[0][2 * np],     a[0], bq[0], bq[1]);
                mma_f16(acc[1][2 * np],     a[1], bq[0], bq[1]);
                mma_f16(acc[0][2 * np + 1], a[0], bq[2], bq[3]);
                mma_f16(acc[1][2 * np + 1], a[1], bq[2], bq[3]);
            }
        }

        slot++; if (slot >= STAGES) slot = 0;
    }

    // ---- epilogue: acc + bias -> out ----
    float2 bv[8];
#pragma unroll
    for (int nf = 0; nf < 8; nf++) {
        const float* bp = g_bias + n0 + wn * 64 + nf * 8 + tig * 2;
        bv[nf] = make_float2(bp[0], bp[1]);
    }
#pragma unroll
    for (int mf = 0; mf < 2; mf++) {
        int r0 = m0 + wm * 32 + mf * 16 + gid;
#pragma unroll
        for (int nf = 0; nf < 8; nf++) {
            int c = n0 + wn * 64 + nf * 8 + tig * 2;
            float2 v0 = make_float2(acc[mf][nf][0] + bv[nf].x,
                                    acc[mf][nf][1] + bv[nf].y);
            float2 v1 = make_float2(acc[mf][nf][2] + bv[nf].x,
                                    acc[mf][nf][3] + bv[nf].y);
            *(float2*)(out + (size_t)r0 * OUT_F + c)       = v0;
            *(float2*)(out + (size_t)(r0 + 8) * OUT_F + c) = v1;
        }
    }
}

// ------------------------------- launcher -----------------------------------

extern "C" void kernel_launch(void* const* d_in, const int* in_sizes, int n_in,
                              void* d_out, int out_size) {
    // Identify inputs by element count (robust to metadata ordering):
    //   x: 16777216;  W_*: 1048576 each;  b_*: 1024 each (OUT_Q)
    const float* x = nullptr;
    const float* W[4] = {nullptr, nullptr, nullptr, nullptr};
    const float* b[4] = {nullptr, nullptr, nullptr, nullptr};
    int wn = 0, bn = 0;
    for (int i = 0; i < n_in; i++) {
        if (in_sizes[i] == BATCH * IN_F)    x = (const float*)d_in[i];
        else if (in_sizes[i] == W_ELEMS)    { if (wn < 4) W[wn++] = (const float*)d_in[i]; }
        else if (in_sizes[i] == QOUT)       { if (bn < 4) b[bn++] = (const float*)d_in[i]; }
    }
    if (!x || wn != 4 || bn != 4) return;

    cudaFuncSetAttribute(k_gemm, cudaFuncAttributeMaxDynamicSharedMemorySize,
                         SMEM_TOTAL);

    k_half_x<<<(BATCH * IN_F / 4) / 256, 256>>>(x);
    k_weff<<<(int)(((size_t)OUT_F * IN_F / 4) / 256), 256>>>(W[0], W[1], W[2], W[3]);
    k_bias<<<OUT_F / 256, 256>>>(b[0], b[1], b[2], b[3]);

    dim3 grid(OUT_F / BN, BATCH / BM);
    k_gemm<<<grid, THREADS, SMEM_TOTAL>>>((float*)d_out);
}